// round 4
// baseline (speedup 1.0000x reference)
#include <cuda_runtime.h>
#include <math.h>

// Problem constants
#define N_CAPS 64
#define CAPS_DIM 16
#define OUT_DIM 128
#define P_DIM 1152
#define BATCH 256
#define BO (BATCH * OUT_DIM)       // 32768
#define PSPLIT 24
#define PCHUNK (P_DIM / PSPLIT)    // 48

// Scratch (no cudaMalloc allowed)
__device__ __align__(16) float g_partial[PSPLIT * BO];          // 3 MB
__device__ __align__(16) float g_wsum [N_CAPS * OUT_DIM];       // [n][o]
__device__ __align__(16) float g_wsumT[OUT_DIM * N_CAPS];       // [o][n]

// ---------------------------------------------------------------------------
// Kernel 1 (fused): grid (32, PSPLIT+1) x 256.
//  y < PSPLIT : X partials. x is (P, B, O) => matrix (P, 32768 floats).
//  y == PSPLIT: Wsum[n,o] = sum_c w[n,c,o], written in both layouts.
// ---------------------------------------------------------------------------
__global__ void __launch_bounds__(256) reduce_x_kernel(const float4* __restrict__ x4,
                                                       const float4* __restrict__ w4) {
    int chunk = blockIdx.y;

    if (chunk == PSPLIT) {
        int i = blockIdx.x * blockDim.x + threadIdx.x;   // float4 index into Wsum
        if (i >= N_CAPS * (OUT_DIM / 4)) return;
        int n  = i >> 5;                                 // 32 float4 per row
        int o4 = i & 31;
        const float4* base = w4 + (size_t)n * (CAPS_DIM * OUT_DIM / 4) + o4;
        float4 acc = make_float4(0.f, 0.f, 0.f, 0.f);
#pragma unroll
        for (int c = 0; c < CAPS_DIM; ++c) {
            float4 v = __ldg(&base[c * (OUT_DIM / 4)]);
            acc.x += v.x; acc.y += v.y; acc.z += v.z; acc.w += v.w;
        }
        reinterpret_cast<float4*>(g_wsum)[i] = acc;
        int o = o4 * 4;
        g_wsumT[(o + 0) * N_CAPS + n] = acc.x;
        g_wsumT[(o + 1) * N_CAPS + n] = acc.y;
        g_wsumT[(o + 2) * N_CAPS + n] = acc.z;
        g_wsumT[(o + 3) * N_CAPS + n] = acc.w;
        return;
    }

    int col = blockIdx.x * blockDim.x + threadIdx.x;     // 0..8191 (float4 units)
    const float4* base = x4 + (size_t)(chunk * PCHUNK) * (BO / 4) + col;

    float4 acc = make_float4(0.f, 0.f, 0.f, 0.f);
#pragma unroll 8
    for (int p = 0; p < PCHUNK; ++p) {
        float4 v = __ldcs(&base[(size_t)p * (BO / 4)]);
        acc.x += v.x; acc.y += v.y; acc.z += v.z; acc.w += v.w;
    }
    reinterpret_cast<float4*>(g_partial)[chunk * (BO / 4) + col] = acc;
}

// ---------------------------------------------------------------------------
// Kernel 2: routing. One block per batch element, 128 threads (thread t = o).
//   xp[b,n,o] = X[o]*W[n,o]  (never materialized)
//   s_o  = X[o] * sum_n c_n W[n,o]        (wregs from g_wsumT, float4)
//   rp_o = scale * s_o * X[o]             (128 floats in shared)
//   logits_n += sum_o rp_o W[n,o]         (threads t<64, W rows via L1 float4)
// ---------------------------------------------------------------------------
__global__ void __launch_bounds__(128) routing_kernel(float* __restrict__ out) {
    const int b = blockIdx.x;
    const int t = threadIdx.x;
    const int lane = t & 31;
    const int wid  = t >> 5;

    __shared__ float shrp[OUT_DIM];   // rp vector
    __shared__ float shc[N_CAPS];     // coeffs
    __shared__ float shred[4];
    __shared__ float shm2[2], shs2[2];
    __shared__ float shscale;

    // Finalize X[b, t] from the PSPLIT partials
    float X = 0.f;
#pragma unroll
    for (int ch = 0; ch < PSPLIT; ++ch)
        X += g_partial[ch * BO + b * OUT_DIM + t];

    // W column for this o: wreg[n] = Wsum[n][t], via transposed layout (float4)
    float wreg[N_CAPS];
    {
        const float4* wt4 = reinterpret_cast<const float4*>(g_wsumT) + t * (N_CAPS / 4);
#pragma unroll
        for (int i = 0; i < N_CAPS / 4; ++i) {
            float4 v = __ldg(&wt4[i]);
            wreg[4 * i + 0] = v.x; wreg[4 * i + 1] = v.y;
            wreg[4 * i + 2] = v.z; wreg[4 * i + 3] = v.w;
        }
    }

    float logit = 0.f;                 // thread t<64 owns logits[t]
    if (t < N_CAPS) shc[t] = 1.0f / N_CAPS;
    __syncthreads();

    // ITERATIONS = 3 -> 2 routing updates, then final squash
    for (int iter = 0; iter < 3; ++iter) {
        // s_o = X * sum_n c_n * W[n,o]
        float s = 0.f;
#pragma unroll
        for (int n = 0; n < N_CAPS; ++n)
            s += shc[n] * wreg[n];
        s *= X;

        // block reduce ||s||^2 over 128 threads
        float sq = s * s;
#pragma unroll
        for (int off = 16; off > 0; off >>= 1)
            sq += __shfl_xor_sync(0xffffffffu, sq, off);
        if (lane == 0) shred[wid] = sq;
        __syncthreads();
        if (t == 0) {
            float tot  = shred[0] + shred[1] + shred[2] + shred[3];
            float norm = sqrtf(tot);
            shscale = norm / (1.0f + tot);   // norm / (1 + norm^2)
        }
        __syncthreads();
        float scale = shscale;

        if (iter == 2) {
            out[b * OUT_DIM + t] = scale * s;   // final squash(coeffs @ xp)
            return;
        }

        // rp to shared
        shrp[t] = scale * s * X;
        __syncthreads();

        // threads t<64: logits[t] += sum_o rp_o * W[t,o]  (row read, L1-hot)
        if (t < N_CAPS) {
            const float4* row4 = reinterpret_cast<const float4*>(g_wsum + t * OUT_DIM);
            const float4* rp4  = reinterpret_cast<const float4*>(shrp);
            float acc = 0.f;
#pragma unroll
            for (int j = 0; j < OUT_DIM / 4; ++j) {
                float4 w4 = __ldg(&row4[j]);
                float4 r4 = rp4[j];
                acc += w4.x * r4.x + w4.y * r4.y + w4.z * r4.z + w4.w * r4.w;
            }
            logit += acc;

            // softmax over 64 logits (warps 0 and 1, fully active)
            float m = logit;
#pragma unroll
            for (int off = 16; off > 0; off >>= 1)
                m = fmaxf(m, __shfl_xor_sync(0xffffffffu, m, off));
            if (lane == 0) shm2[wid] = m;
        }
        __syncthreads();
        if (t < N_CAPS) {
            float M = fmaxf(shm2[0], shm2[1]);
            float e = __expf(logit - M);
            float sm = e;
#pragma unroll
            for (int off = 16; off > 0; off >>= 1)
                sm += __shfl_xor_sync(0xffffffffu, sm, off);
            if (lane == 0) shs2[wid] = sm;
            // stash e in shrp-free slot via register; write coeff after sum known
            __syncwarp();
            shc[t] = e;   // temporarily store numerator
        }
        __syncthreads();
        if (t < N_CAPS) {
            float S = shs2[0] + shs2[1];
            shc[t] = shc[t] / S;
        }
        __syncthreads();
    }
}

// ---------------------------------------------------------------------------
extern "C" void kernel_launch(void* const* d_in, const int* in_sizes, int n_in,
                              void* d_out, int out_size) {
    const float* x = (const float*)d_in[0];             // (1152, 256, 128)
    const float* w = (const float*)d_in[1];             // (64, 16, 128)
    float* out = (float*)d_out;                         // (256, 1, 128)

    dim3 g1(32, PSPLIT + 1);
    reduce_x_kernel<<<g1, 256>>>(reinterpret_cast<const float4*>(x),
                                 reinterpret_cast<const float4*>(w));
    routing_kernel<<<BATCH, 128>>>(out);
}

// round 5
// speedup vs baseline: 1.1221x; 1.1221x over previous
#include <cuda_runtime.h>
#include <math.h>

// Problem constants
#define N_CAPS 64
#define CAPS_DIM 16
#define OUT_DIM 128
#define P_DIM 1152
#define BATCH 256
#define BO (BATCH * OUT_DIM)       // 32768
#define PSPLIT 24
#define PCHUNK (P_DIM / PSPLIT)    // 48
#define WSTRIDE 129                // padded row stride for shared Wsum

// Scratch (no cudaMalloc allowed)
__device__ __align__(16) float g_partial[PSPLIT * BO];     // 3 MB
__device__ __align__(16) float g_wsum[N_CAPS * OUT_DIM];   // [n][o], 32 KB

// ---------------------------------------------------------------------------
// Kernel 1 (fused): grid (32, PSPLIT+1) x 256.
//  y < PSPLIT : X partials. x is (P, B, O) => matrix (P, 32768 floats).
//  y == PSPLIT: Wsum[n,o] = sum_c w[n,c,o] (float4), hidden inside the
//               HBM-bound reduction.
// ---------------------------------------------------------------------------
__global__ void __launch_bounds__(256) reduce_x_kernel(const float4* __restrict__ x4,
                                                       const float4* __restrict__ w4) {
    int chunk = blockIdx.y;

    if (chunk == PSPLIT) {
        int i = blockIdx.x * blockDim.x + threadIdx.x;   // float4 index into Wsum
        if (i >= N_CAPS * (OUT_DIM / 4)) return;
        int n  = i >> 5;                                 // 32 float4 per row
        int o4 = i & 31;
        const float4* base = w4 + (size_t)n * (CAPS_DIM * OUT_DIM / 4) + o4;
        float4 acc = make_float4(0.f, 0.f, 0.f, 0.f);
#pragma unroll
        for (int c = 0; c < CAPS_DIM; ++c) {
            float4 v = __ldg(&base[c * (OUT_DIM / 4)]);
            acc.x += v.x; acc.y += v.y; acc.z += v.z; acc.w += v.w;
        }
        reinterpret_cast<float4*>(g_wsum)[i] = acc;
        return;
    }

    int col = blockIdx.x * blockDim.x + threadIdx.x;     // 0..8191 (float4 units)
    const float4* base = x4 + (size_t)(chunk * PCHUNK) * (BO / 4) + col;

    float4 acc = make_float4(0.f, 0.f, 0.f, 0.f);
#pragma unroll 8
    for (int p = 0; p < PCHUNK; ++p) {
        float4 v = __ldcs(&base[(size_t)p * (BO / 4)]);
        acc.x += v.x; acc.y += v.y; acc.z += v.z; acc.w += v.w;
    }
    reinterpret_cast<float4*>(g_partial)[chunk * (BO / 4) + col] = acc;
}

// ---------------------------------------------------------------------------
// Kernel 2: routing. One block per batch element, 128 threads (thread t = o).
// Whole Wsum lives in padded shared (stride 129, conflict-free both ways).
//   s_o  = X[o] * sum_n c_n W[n,o]       (column LDS)
//   rp_o = scale * s_o * X[o]            (shared vector)
//   logits_n += sum_o rp_o W[n,o]        (row LDS, threads t<64)
// ---------------------------------------------------------------------------
__global__ void __launch_bounds__(128) routing_kernel(float* __restrict__ out) {
    const int b = blockIdx.x;
    const int t = threadIdx.x;
    const int lane = t & 31;
    const int wid  = t >> 5;

    __shared__ float sh_w[N_CAPS * WSTRIDE];  // padded Wsum (33 KB)
    __shared__ float shrp[OUT_DIM];           // rp vector
    __shared__ float shc[N_CAPS];             // coeffs
    __shared__ float shred[4];
    __shared__ float shm2[2], shs2[2];
    __shared__ float shscale;

    // Cooperative load of Wsum into padded shared (16 float4 per thread)
    {
        const float4* w4 = reinterpret_cast<const float4*>(g_wsum);
#pragma unroll
        for (int i4 = t; i4 < N_CAPS * (OUT_DIM / 4); i4 += 128) {
            float4 v = __ldg(&w4[i4]);
            int n = i4 >> 5;
            int o = (i4 & 31) * 4;
            float* dst = &sh_w[n * WSTRIDE + o];
            dst[0] = v.x; dst[1] = v.y; dst[2] = v.z; dst[3] = v.w;
        }
    }

    // Finalize X[b, t] from the PSPLIT partials (overlaps with W load)
    float X = 0.f;
#pragma unroll
    for (int ch = 0; ch < PSPLIT; ++ch)
        X += g_partial[ch * BO + b * OUT_DIM + t];

    if (t < N_CAPS) shc[t] = 1.0f / N_CAPS;
    float logit = 0.f;                 // thread t<64 owns logits[t]
    __syncthreads();

    // ITERATIONS = 3 -> 2 routing updates, then final squash
    for (int iter = 0; iter < 3; ++iter) {
        // s_o = X * sum_n c_n * W[n,o]   (column read: lanes consecutive)
        float s = 0.f;
#pragma unroll
        for (int n = 0; n < N_CAPS; ++n)
            s += shc[n] * sh_w[n * WSTRIDE + t];
        s *= X;

        // block reduce ||s||^2 over 128 threads
        float sq = s * s;
#pragma unroll
        for (int off = 16; off > 0; off >>= 1)
            sq += __shfl_xor_sync(0xffffffffu, sq, off);
        if (lane == 0) shred[wid] = sq;
        __syncthreads();
        if (t == 0) {
            float tot  = shred[0] + shred[1] + shred[2] + shred[3];
            float norm = sqrtf(tot);
            shscale = norm / (1.0f + tot);   // norm / (1 + norm^2)
        }
        __syncthreads();
        float scale = shscale;

        if (iter == 2) {
            out[b * OUT_DIM + t] = scale * s;   // final squash(coeffs @ xp)
            return;
        }

        // rp to shared
        shrp[t] = scale * s * X;
        __syncthreads();

        // threads t<64: logits[t] += sum_o rp_o * W[t,o]  (row read: (t+j)%32)
        if (t < N_CAPS) {
            const float* wrow = &sh_w[t * WSTRIDE];
            float acc = 0.f;
#pragma unroll 8
            for (int j = 0; j < OUT_DIM; ++j)
                acc += shrp[j] * wrow[j];
            logit += acc;

            // softmax over 64 logits (warps 0 and 1, fully active)
            float m = logit;
#pragma unroll
            for (int off = 16; off > 0; off >>= 1)
                m = fmaxf(m, __shfl_xor_sync(0xffffffffu, m, off));
            if (lane == 0) shm2[wid] = m;
        }
        __syncthreads();
        if (t < N_CAPS) {
            float M = fmaxf(shm2[0], shm2[1]);
            float e = __expf(logit - M);
            float sm = e;
#pragma unroll
            for (int off = 16; off > 0; off >>= 1)
                sm += __shfl_xor_sync(0xffffffffu, sm, off);
            if (lane == 0) shs2[wid] = sm;
            __syncwarp();
            shc[t] = e;   // numerator; normalized after sums combine
        }
        __syncthreads();
        if (t < N_CAPS) {
            float S = shs2[0] + shs2[1];
            shc[t] = shc[t] / S;
        }
        __syncthreads();
    }
}

// ---------------------------------------------------------------------------
extern "C" void kernel_launch(void* const* d_in, const int* in_sizes, int n_in,
                              void* d_out, int out_size) {
    const float* x = (const float*)d_in[0];             // (1152, 256, 128)
    const float* w = (const float*)d_in[1];             // (64, 16, 128)
    float* out = (float*)d_out;                         // (256, 1, 128)

    dim3 g1(32, PSPLIT + 1);
    reduce_x_kernel<<<g1, 256>>>(reinterpret_cast<const float4*>(x),
                                 reinterpret_cast<const float4*>(w));
    routing_kernel<<<BATCH, 128>>>(out);
}